// round 9
// baseline (speedup 1.0000x reference)
#include <cuda_runtime.h>
#include <cuda_bf16.h>
#include <cstdint>

// Problem shape (fixed by the dataset)
#define MT 8192
#define NT 4096
#define KTOT 4096

// GEMM tiling
#define BM 256
#define BN 256
#define BK 64                 // bf16 elems per stage -> 128B rows
#define NITER (KTOT / BK)     // 64
#define NBUF 3
#define STAGE_BYTES ((BM + BN) * BK * 2)   // 65536
#define SMEM_TOTAL (NBUF * STAGE_BYTES)    // 196608

// Packed bf16 operands (static device globals — no allocs)
__device__ __align__(16) __nv_bfloat16 g_a[(size_t)MT * KTOT];  // 64 MB
__device__ __align__(16) __nv_bfloat16 g_w[(size_t)NT * KTOT];  // 32 MB

// ---------------------------------------------------------------------------
// PTX helpers (baseline-PTX only: cp.async, ldmatrix, mma.sync bf16)
// ---------------------------------------------------------------------------
__device__ __forceinline__ uint32_t smem_u32(const void* p) {
    uint32_t a;
    asm("{ .reg .u64 t; cvta.to.shared.u64 t, %1; cvt.u32.u64 %0, t; }" : "=r"(a) : "l"(p));
    return a;
}
#define CP_ASYNC16(dst, src) \
    asm volatile("cp.async.cg.shared.global [%0], [%1], 16;" :: "r"(dst), "l"(src) : "memory")
#define CP_COMMIT()  asm volatile("cp.async.commit_group;" ::: "memory")
#define CP_WAIT(n)   asm volatile("cp.async.wait_group %0;" :: "n"(n) : "memory")

// byte-offset swizzle for 128B rows (8 x 16B chunks): chunk ^= (row & 7)
#define SWZ(o) ((o) ^ (((o) >> 3) & 0x70))

__device__ __forceinline__ void ldsm_x4(uint32_t& r0, uint32_t& r1, uint32_t& r2, uint32_t& r3,
                                        uint32_t addr) {
    asm volatile("ldmatrix.sync.aligned.m8n8.x4.shared.b16 {%0,%1,%2,%3}, [%4];"
                 : "=r"(r0), "=r"(r1), "=r"(r2), "=r"(r3) : "r"(addr));
}
__device__ __forceinline__ void mma_bf16(float* c, const uint32_t* a, const uint32_t* b) {
    asm volatile(
        "mma.sync.aligned.m16n8k16.row.col.f32.bf16.bf16.f32 "
        "{%0,%1,%2,%3}, {%4,%5,%6,%7}, {%8,%9}, {%0,%1,%2,%3};"
        : "+f"(c[0]), "+f"(c[1]), "+f"(c[2]), "+f"(c[3])
        : "r"(a[0]), "r"(a[1]), "r"(a[2]), "r"(a[3]), "r"(b[0]), "r"(b[1]));
}

// ---------------------------------------------------------------------------
// Fused pre-pass: blocks [0, XB) quantize x fp32 -> bf16 (exact integers,
// matching clip(round(x/input_scale),-128,127), rintf = half-even like jnp);
// blocks [XB, XB+WB) convert weight int32 -> bf16 (exact).
// ---------------------------------------------------------------------------
#define XB (MT * KTOT / 8 / 256)   // 16384 blocks
#define WB (NT * KTOT / 8 / 256)   // 8192 blocks

__global__ void prepack_kernel(const float4* __restrict__ x,
                               const int4* __restrict__ w,
                               const float* __restrict__ in_scale) {
    int b = blockIdx.x;
    __nv_bfloat16 o[8];
    if (b < XB) {
        int i = b * 256 + threadIdx.x;
        float s = *in_scale;
        float4 v0 = x[i * 2], v1 = x[i * 2 + 1];
        o[0] = __float2bfloat16(fminf(fmaxf(rintf(v0.x / s), -128.0f), 127.0f));
        o[1] = __float2bfloat16(fminf(fmaxf(rintf(v0.y / s), -128.0f), 127.0f));
        o[2] = __float2bfloat16(fminf(fmaxf(rintf(v0.z / s), -128.0f), 127.0f));
        o[3] = __float2bfloat16(fminf(fmaxf(rintf(v0.w / s), -128.0f), 127.0f));
        o[4] = __float2bfloat16(fminf(fmaxf(rintf(v1.x / s), -128.0f), 127.0f));
        o[5] = __float2bfloat16(fminf(fmaxf(rintf(v1.y / s), -128.0f), 127.0f));
        o[6] = __float2bfloat16(fminf(fmaxf(rintf(v1.z / s), -128.0f), 127.0f));
        o[7] = __float2bfloat16(fminf(fmaxf(rintf(v1.w / s), -128.0f), 127.0f));
        *(uint4*)(g_a + (size_t)i * 8) = *(const uint4*)o;
    } else {
        int i = (b - XB) * 256 + threadIdx.x;
        int4 v0 = w[i * 2], v1 = w[i * 2 + 1];
        o[0] = __float2bfloat16((float)v0.x);
        o[1] = __float2bfloat16((float)v0.y);
        o[2] = __float2bfloat16((float)v0.z);
        o[3] = __float2bfloat16((float)v0.w);
        o[4] = __float2bfloat16((float)v1.x);
        o[5] = __float2bfloat16((float)v1.y);
        o[6] = __float2bfloat16((float)v1.z);
        o[7] = __float2bfloat16((float)v1.w);
        *(uint4*)(g_w + (size_t)i * 8) = *(const uint4*)o;
    }
}

// ---------------------------------------------------------------------------
// bf16 HMMA GEMM: C[m,n] = sum_k A[m,k]*W[n,k] (f32 acc), then * (is*ws).
// BM=256 x BN=256 per CTA, 512 threads = 4(m) x 4(n) warps of 64x64.
// 128 B/MMA shared traffic (vs 192 at 64x32): tensor pipe is sole bound.
// Smem: 128B rows, SWZ swizzle; stage s at s*65536, A then B (at +32768).
// ---------------------------------------------------------------------------
extern __shared__ char dyn_smem[];

__global__ __launch_bounds__(512, 1)
void gemm_hmma_kernel(float* __restrict__ C,
                      const float* __restrict__ w_scale,
                      const float* __restrict__ in_scale) {
    const uint32_t sb = smem_u32(dyn_smem);
    const int tid = threadIdx.x;
    const int wid = tid >> 5;
    const int lid = tid & 31;
    const int mw = wid >> 2;          // 0..3  (64 rows each)
    const int nw = wid & 3;           // 0..3  (64 cols each)

    const int tiles_m = MT / BM;      // 32, bm-fastest for L2 reuse of B panel
    const int bm = blockIdx.x % tiles_m;
    const int bn = blockIdx.x / tiles_m;

    const __nv_bfloat16* __restrict__ Ab = g_a + (size_t)(bm * BM) * KTOT;
    const __nv_bfloat16* __restrict__ Bb = g_w + (size_t)(bn * BN) * KTOT;

    // ---- cp.async staging: 4096 chunks of 16B per stage, 8 per thread ----
    auto load_stage = [&](int kt, int buf) {
        const uint32_t base = sb + buf * STAGE_BYTES;
        const int kof = kt * BK;
#pragma unroll
        for (int it = 0; it < 8; ++it) {
            int q = tid + it * 512;
            uint32_t dst;
            const __nv_bfloat16* src;
            if (q < 2048) {           // A: 256 rows x 8 chunks
                int row = q >> 3, c = q & 7;
                dst = base + SWZ(row * 128 + c * 16);
                src = Ab + (size_t)row * KTOT + kof + c * 8;
            } else {                  // B: 256 rows x 8 chunks
                int p = q - 2048;
                int row = p >> 3, c = p & 7;
                dst = base + BM * BK * 2 + SWZ(row * 128 + c * 16);
                src = Bb + (size_t)row * KTOT + kof + c * 8;
            }
            CP_ASYNC16(dst, src);
        }
        CP_COMMIT();
    };

    // ---- per-lane ldmatrix row/chunk precompute ----
    const int rlA = lid & 15;         // A x4: m16 x k16
    const int cbA = lid >> 4;
    const int rlB = (lid & 7) | ((lid >> 4) << 3);   // B x4: n16 x k16
    const int cbB = (lid >> 3) & 1;

    uint32_t aoff[4]; int asw[4];
#pragma unroll
    for (int mi = 0; mi < 4; ++mi) {
        int r = mw * 64 + mi * 16 + rlA;
        aoff[mi] = r * 128; asw[mi] = r & 7;
    }
    uint32_t boff[4]; int bsw[4];
#pragma unroll
    for (int np = 0; np < 4; ++np) {
        int r = nw * 64 + np * 16 + rlB;
        boff[np] = BM * BK * 2 + r * 128; bsw[np] = r & 7;
    }

    float acc[4][8][4];
#pragma unroll
    for (int mi = 0; mi < 4; ++mi)
#pragma unroll
        for (int nt = 0; nt < 8; ++nt)
#pragma unroll
            for (int j = 0; j < 4; ++j) acc[mi][nt][j] = 0.0f;

    // ---- pipeline prologue: 2 stages in flight ----
    load_stage(0, 0);
    load_stage(1, 1);

    for (int kt = 0; kt < NITER; ++kt) {
        if (kt < NITER - 1) { CP_WAIT(1); } else { CP_WAIT(0); }
        __syncthreads();

        if (kt + 2 < NITER) load_stage(kt + 2, (kt + 2) % NBUF);

        const uint32_t stage = sb + (kt % NBUF) * STAGE_BYTES;
#pragma unroll
        for (int ks = 0; ks < 4; ++ks) {
            uint32_t af[4][4], bf[8][2];
            const int cA = 2 * ks + cbA;
            const int cB = 2 * ks + cbB;
#pragma unroll
            for (int mi = 0; mi < 4; ++mi)
                ldsm_x4(af[mi][0], af[mi][1], af[mi][2], af[mi][3],
                        stage + aoff[mi] + ((cA ^ asw[mi]) << 4));
#pragma unroll
            for (int np = 0; np < 4; ++np) {
                uint32_t r0, r1, r2, r3;
                ldsm_x4(r0, r1, r2, r3, stage + boff[np] + ((cB ^ bsw[np]) << 4));
                bf[np * 2 + 0][0] = r0; bf[np * 2 + 0][1] = r1;
                bf[np * 2 + 1][0] = r2; bf[np * 2 + 1][1] = r3;
            }
#pragma unroll
            for (int mi = 0; mi < 4; ++mi)
#pragma unroll
                for (int nt = 0; nt < 8; ++nt)
                    mma_bf16(acc[mi][nt], af[mi], bf[nt]);
        }
    }

    // ---- epilogue: scale and store ----
    const float sc = (*w_scale) * (*in_scale);
    const int g = lid >> 2, tig = lid & 3;
    const int m_base = bm * BM + mw * 64;
    const int n_base = bn * BN + nw * 64;
#pragma unroll
    for (int mi = 0; mi < 4; ++mi) {
#pragma unroll
        for (int nt = 0; nt < 8; ++nt) {
            const int r0 = m_base + mi * 16 + g;
            const int col = n_base + nt * 8 + 2 * tig;
            float2 v0, v1;
            v0.x = acc[mi][nt][0] * sc; v0.y = acc[mi][nt][1] * sc;
            v1.x = acc[mi][nt][2] * sc; v1.y = acc[mi][nt][3] * sc;
            *(float2*)(C + (size_t)r0 * NT + col)       = v0;
            *(float2*)(C + (size_t)(r0 + 8) * NT + col) = v1;
        }
    }
}

// ---------------------------------------------------------------------------
// Harness entry
// Inputs: x fp32 [4,2048,4096], weight int32 [4096,4096], scale [1], input_scale [1]
// Output: fp32 [4,2048,4096]
// ---------------------------------------------------------------------------
extern "C" void kernel_launch(void* const* d_in, const int* in_sizes, int n_in,
                              void* d_out, int out_size) {
    const float* x        = (const float*)d_in[0];
    const int*   w        = (const int*)d_in[1];
    const float* w_scale  = (const float*)d_in[2];
    const float* in_scale = (const float*)d_in[3];
    float* out = (float*)d_out;
    (void)in_sizes; (void)n_in; (void)out_size;

    cudaFuncSetAttribute(gemm_hmma_kernel,
                         cudaFuncAttributeMaxDynamicSharedMemorySize, SMEM_TOTAL);

    prepack_kernel<<<XB + WB, 256>>>((const float4*)x, (const int4*)w, in_scale);

    const int grid = (MT / BM) * (NT / BN);   // 32 * 16 = 512
    gemm_hmma_kernel<<<grid, 512, SMEM_TOTAL>>>(out, w_scale, in_scale);
}

// round 11
// speedup vs baseline: 3.7064x; 3.7064x over previous
#include <cuda_runtime.h>
#include <cuda_bf16.h>
#include <cstdint>

// Problem shape (fixed by the dataset)
#define MT 8192
#define NT 4096
#define KTOT 4096

// GEMM tiling
#define BM 128
#define BN 128
#define BK 64                 // bf16 elems per stage -> 128B rows
#define KSTAGES (KTOT / BK)   // 64 k-stages per tile
#define NBUF 3
#define STAGE_BYTES ((BM + BN) * BK * 2)   // 32768
#define SMEM_TOTAL (NBUF * STAGE_BYTES)    // 98304  -> 2 CTAs/SM
#define TILES_M (MT / BM)     // 64
#define NTILES  ((MT / BM) * (NT / BN))    // 2048
#define GRID    296           // 2 persistent CTAs per SM

// Packed bf16 operands (static device globals — no allocs)
__device__ __align__(16) __nv_bfloat16 g_a[(size_t)MT * KTOT];  // 64 MB
__device__ __align__(16) __nv_bfloat16 g_w[(size_t)NT * KTOT];  // 32 MB

// ---------------------------------------------------------------------------
// PTX helpers (baseline-PTX only: cp.async, ldmatrix, mma.sync bf16)
// ---------------------------------------------------------------------------
__device__ __forceinline__ uint32_t smem_u32(const void* p) {
    uint32_t a;
    asm("{ .reg .u64 t; cvta.to.shared.u64 t, %1; cvt.u32.u64 %0, t; }" : "=r"(a) : "l"(p));
    return a;
}
#define CP_ASYNC16(dst, src) \
    asm volatile("cp.async.cg.shared.global [%0], [%1], 16;" :: "r"(dst), "l"(src) : "memory")
#define CP_COMMIT()  asm volatile("cp.async.commit_group;" ::: "memory")
#define CP_WAIT(n)   asm volatile("cp.async.wait_group %0;" :: "n"(n) : "memory")

// byte-offset swizzle for 128B rows (8 x 16B chunks): chunk ^= (row & 7)
#define SWZ(o) ((o) ^ (((o) >> 3) & 0x70))

__device__ __forceinline__ void ldsm_x4(uint32_t& r0, uint32_t& r1, uint32_t& r2, uint32_t& r3,
                                        uint32_t addr) {
    asm volatile("ldmatrix.sync.aligned.m8n8.x4.shared.b16 {%0,%1,%2,%3}, [%4];"
                 : "=r"(r0), "=r"(r1), "=r"(r2), "=r"(r3) : "r"(addr));
}
__device__ __forceinline__ void mma_bf16(float* c, const uint32_t* a, const uint32_t* b) {
    asm volatile(
        "mma.sync.aligned.m16n8k16.row.col.f32.bf16.bf16.f32 "
        "{%0,%1,%2,%3}, {%4,%5,%6,%7}, {%8,%9}, {%0,%1,%2,%3};"
        : "+f"(c[0]), "+f"(c[1]), "+f"(c[2]), "+f"(c[3])
        : "r"(a[0]), "r"(a[1]), "r"(a[2]), "r"(a[3]), "r"(b[0]), "r"(b[1]));
}

// ---------------------------------------------------------------------------
// Fused pre-pass: blocks [0, XB) quantize x fp32 -> bf16 (exact integers,
// matching clip(round(x/input_scale),-128,127), rintf = half-even like jnp);
// blocks [XB, XB+WB) convert weight int32 -> bf16 (exact).
// ---------------------------------------------------------------------------
#define XB (MT * KTOT / 8 / 256)   // 16384 blocks
#define WB (NT * KTOT / 8 / 256)   // 8192 blocks

__global__ void prepack_kernel(const float4* __restrict__ x,
                               const int4* __restrict__ w,
                               const float* __restrict__ in_scale) {
    int b = blockIdx.x;
    __nv_bfloat16 o[8];
    if (b < XB) {
        int i = b * 256 + threadIdx.x;
        float s = *in_scale;
        float4 v0 = x[i * 2], v1 = x[i * 2 + 1];
        o[0] = __float2bfloat16(fminf(fmaxf(rintf(v0.x / s), -128.0f), 127.0f));
        o[1] = __float2bfloat16(fminf(fmaxf(rintf(v0.y / s), -128.0f), 127.0f));
        o[2] = __float2bfloat16(fminf(fmaxf(rintf(v0.z / s), -128.0f), 127.0f));
        o[3] = __float2bfloat16(fminf(fmaxf(rintf(v0.w / s), -128.0f), 127.0f));
        o[4] = __float2bfloat16(fminf(fmaxf(rintf(v1.x / s), -128.0f), 127.0f));
        o[5] = __float2bfloat16(fminf(fmaxf(rintf(v1.y / s), -128.0f), 127.0f));
        o[6] = __float2bfloat16(fminf(fmaxf(rintf(v1.z / s), -128.0f), 127.0f));
        o[7] = __float2bfloat16(fminf(fmaxf(rintf(v1.w / s), -128.0f), 127.0f));
        *(uint4*)(g_a + (size_t)i * 8) = *(const uint4*)o;
    } else {
        int i = (b - XB) * 256 + threadIdx.x;
        int4 v0 = w[i * 2], v1 = w[i * 2 + 1];
        o[0] = __float2bfloat16((float)v0.x);
        o[1] = __float2bfloat16((float)v0.y);
        o[2] = __float2bfloat16((float)v0.z);
        o[3] = __float2bfloat16((float)v0.w);
        o[4] = __float2bfloat16((float)v1.x);
        o[5] = __float2bfloat16((float)v1.y);
        o[6] = __float2bfloat16((float)v1.z);
        o[7] = __float2bfloat16((float)v1.w);
        *(uint4*)(g_w + (size_t)i * 8) = *(const uint4*)o;
    }
}

// ---------------------------------------------------------------------------
// Persistent bf16 HMMA GEMM: each CTA walks tiles bid, bid+296, ... with a
// continuous cp.async pipeline across tile boundaries (no per-tile prologue
// drain; epilogue stores overlap the next tile's loads).
// BM=128 x BN=128 per tile, 256 threads = 2(m) x 4(n) warps of 64x32.
// Smem: 128B rows, SWZ swizzle; stage s at s*32768, A then B (at +16384).
// ---------------------------------------------------------------------------
extern __shared__ char dyn_smem[];

__global__ __launch_bounds__(256, 2)
void gemm_hmma_kernel(float* __restrict__ C,
                      const float* __restrict__ w_scale,
                      const float* __restrict__ in_scale) {
    const uint32_t sb = smem_u32(dyn_smem);
    const int tid = threadIdx.x;
    const int wid = tid >> 5;
    const int lid = tid & 31;
    const int mw = wid >> 2;          // 0..1  (64 rows each)
    const int nw = wid & 3;           // 0..3  (32 cols each)
    const int bid = blockIdx.x;

    const int my_tiles = (NTILES - bid + GRID - 1) / GRID;
    const int S = my_tiles * KSTAGES;     // total k-stages this CTA processes

    // load_stage for global stage g (tile seq g/64, k-chunk g%64)
    auto load_stage = [&](int g) {
        const int seq = g >> 6;
        const int kof = (g & 63) * BK;
        const int t   = bid + seq * GRID;
        const __nv_bfloat16* __restrict__ Ab = g_a + (size_t)((t & (TILES_M - 1)) * BM) * KTOT;
        const __nv_bfloat16* __restrict__ Bb = g_w + (size_t)((t >> 6) * BN) * KTOT;
        const uint32_t base = sb + (g % NBUF) * STAGE_BYTES;
#pragma unroll
        for (int it = 0; it < 8; ++it) {
            int q = tid + it * 256;
            uint32_t dst;
            const __nv_bfloat16* src;
            if (q < 1024) {           // A: 128 rows x 8 chunks
                int row = q >> 3, c = q & 7;
                dst = base + SWZ(row * 128 + c * 16);
                src = Ab + (size_t)row * KTOT + kof + c * 8;
            } else {                  // B: 128 rows x 8 chunks
                int p = q - 1024;
                int row = p >> 3, c = p & 7;
                dst = base + BM * BK * 2 + SWZ(row * 128 + c * 16);
                src = Bb + (size_t)row * KTOT + kof + c * 8;
            }
            CP_ASYNC16(dst, src);
        }
        CP_COMMIT();
    };

    // ---- per-lane ldmatrix row/chunk precompute ----
    const int rlA = lid & 15;         // A x4: m16 x k16
    const int cbA = lid >> 4;
    const int rlB = (lid & 7) | ((lid >> 4) << 3);   // B x4: n16 x k16
    const int cbB = (lid >> 3) & 1;

    uint32_t aoff[4]; int asw[4];
#pragma unroll
    for (int mi = 0; mi < 4; ++mi) {
        int r = mw * 64 + mi * 16 + rlA;
        aoff[mi] = r * 128; asw[mi] = r & 7;
    }
    uint32_t boff[2]; int bsw[2];
#pragma unroll
    for (int np = 0; np < 2; ++np) {
        int r = nw * 32 + np * 16 + rlB;
        boff[np] = BM * BK * 2 + r * 128; bsw[np] = r & 7;
    }

    float acc[4][4][4];
#pragma unroll
    for (int mi = 0; mi < 4; ++mi)
#pragma unroll
        for (int nt = 0; nt < 4; ++nt)
#pragma unroll
            for (int j = 0; j < 4; ++j) acc[mi][nt][j] = 0.0f;

    const float sc = (*w_scale) * (*in_scale);

    // ---- continuous pipeline prologue: 2 stages in flight ----
    load_stage(0);
    load_stage(1);

    for (int g = 0; g < S; ++g) {
        if (g < S - 1) { CP_WAIT(1); } else { CP_WAIT(0); }
        __syncthreads();

        if (g + 2 < S) load_stage(g + 2);

        const uint32_t stage = sb + (g % NBUF) * STAGE_BYTES;
#pragma unroll
        for (int ks = 0; ks < 4; ++ks) {
            uint32_t af[4][4], bf[4][2];
            const int cA = 2 * ks + cbA;
            const int cB = 2 * ks + cbB;
#pragma unroll
            for (int mi = 0; mi < 4; ++mi)
                ldsm_x4(af[mi][0], af[mi][1], af[mi][2], af[mi][3],
                        stage + aoff[mi] + ((cA ^ asw[mi]) << 4));
#pragma unroll
            for (int np = 0; np < 2; ++np) {
                uint32_t r0, r1, r2, r3;
                ldsm_x4(r0, r1, r2, r3, stage + boff[np] + ((cB ^ bsw[np]) << 4));
                bf[np * 2 + 0][0] = r0; bf[np * 2 + 0][1] = r1;
                bf[np * 2 + 1][0] = r2; bf[np * 2 + 1][1] = r3;
            }
#pragma unroll
            for (int mi = 0; mi < 4; ++mi)
#pragma unroll
                for (int nt = 0; nt < 4; ++nt)
                    mma_bf16(acc[mi][nt], af[mi], bf[nt]);
        }

        // ---- tile boundary: epilogue overlaps next tile's in-flight loads ----
        if ((g & 63) == 63) {
            const int t = bid + (g >> 6) * GRID;
            const int g8 = lid >> 2, tig = lid & 3;
            const int m_base = (t & (TILES_M - 1)) * BM + mw * 64;
            const int n_base = (t >> 6) * BN + nw * 32;
#pragma unroll
            for (int mi = 0; mi < 4; ++mi) {
#pragma unroll
                for (int nt = 0; nt < 4; ++nt) {
                    const int r0 = m_base + mi * 16 + g8;
                    const int col = n_base + nt * 8 + 2 * tig;
                    float2 v0, v1;
                    v0.x = acc[mi][nt][0] * sc; v0.y = acc[mi][nt][1] * sc;
                    v1.x = acc[mi][nt][2] * sc; v1.y = acc[mi][nt][3] * sc;
                    *(float2*)(C + (size_t)r0 * NT + col)       = v0;
                    *(float2*)(C + (size_t)(r0 + 8) * NT + col) = v1;
#pragma unroll
                    for (int j = 0; j < 4; ++j) acc[mi][nt][j] = 0.0f;
                }
            }
        }
    }
}

// ---------------------------------------------------------------------------
// Harness entry
// Inputs: x fp32 [4,2048,4096], weight int32 [4096,4096], scale [1], input_scale [1]
// Output: fp32 [4,2048,4096]
// ---------------------------------------------------------------------------
extern "C" void kernel_launch(void* const* d_in, const int* in_sizes, int n_in,
                              void* d_out, int out_size) {
    const float* x        = (const float*)d_in[0];
    const int*   w        = (const int*)d_in[1];
    const float* w_scale  = (const float*)d_in[2];
    const float* in_scale = (const float*)d_in[3];
    float* out = (float*)d_out;
    (void)in_sizes; (void)n_in; (void)out_size;

    cudaFuncSetAttribute(gemm_hmma_kernel,
                         cudaFuncAttributeMaxDynamicSharedMemorySize, SMEM_TOTAL);

    prepack_kernel<<<XB + WB, 256>>>((const float4*)x, (const int4*)w, in_scale);

    gemm_hmma_kernel<<<GRID, 256, SMEM_TOTAL>>>(out, w_scale, in_scale);
}

// round 13
// speedup vs baseline: 4.0034x; 1.0801x over previous
#include <cuda_runtime.h>
#include <cuda_bf16.h>
#include <cstdint>

// Problem shape (fixed by the dataset)
#define MT 8192
#define NT 4096
#define KTOT 4096

// GEMM tiling
#define BM 128
#define BN 128
#define BK 64                 // bf16 elems per stage -> 128B rows
#define NITER (KTOT / BK)     // 64
#define NBUF 3
#define STAGE_BYTES ((BM + BN) * BK * 2)   // 32768
#define SMEM_TOTAL (NBUF * STAGE_BYTES)    // 98304 -> 2 CTAs/SM

// Packed bf16 operands (static device globals — no allocs)
__device__ __align__(16) __nv_bfloat16 g_a[(size_t)MT * KTOT];  // 64 MB
__device__ __align__(16) __nv_bfloat16 g_w[(size_t)NT * KTOT];  // 32 MB

// ---------------------------------------------------------------------------
// PTX helpers (baseline-PTX only: cp.async, ldmatrix, mma.sync bf16)
// ---------------------------------------------------------------------------
__device__ __forceinline__ uint32_t smem_u32(const void* p) {
    uint32_t a;
    asm("{ .reg .u64 t; cvta.to.shared.u64 t, %1; cvt.u32.u64 %0, t; }" : "=r"(a) : "l"(p));
    return a;
}
#define CP_ASYNC16(dst, src) \
    asm volatile("cp.async.cg.shared.global [%0], [%1], 16;" :: "r"(dst), "l"(src) : "memory")
#define CP_COMMIT()  asm volatile("cp.async.commit_group;" ::: "memory")
#define CP_WAIT(n)   asm volatile("cp.async.wait_group %0;" :: "n"(n) : "memory")

// byte-offset swizzle for 128B rows (8 x 16B chunks): chunk ^= (row & 7)
#define SWZ(o) ((o) ^ (((o) >> 3) & 0x70))

__device__ __forceinline__ void ldsm_x4(uint32_t& r0, uint32_t& r1, uint32_t& r2, uint32_t& r3,
                                        uint32_t addr) {
    asm volatile("ldmatrix.sync.aligned.m8n8.x4.shared.b16 {%0,%1,%2,%3}, [%4];"
                 : "=r"(r0), "=r"(r1), "=r"(r2), "=r"(r3) : "r"(addr));
}
__device__ __forceinline__ void mma_bf16(float* c, const uint32_t* a, const uint32_t* b) {
    asm volatile(
        "mma.sync.aligned.m16n8k16.row.col.f32.bf16.bf16.f32 "
        "{%0,%1,%2,%3}, {%4,%5,%6,%7}, {%8,%9}, {%0,%1,%2,%3};"
        : "+f"(c[0]), "+f"(c[1]), "+f"(c[2]), "+f"(c[3])
        : "r"(a[0]), "r"(a[1]), "r"(a[2]), "r"(a[3]), "r"(b[0]), "r"(b[1]));
}

// ---------------------------------------------------------------------------
// Fused pre-pass: blocks [0, XB) quantize x fp32 -> bf16 (exact integers,
// matching clip(round(x/input_scale),-128,127), rintf = half-even like jnp);
// blocks [XB, XB+WB) convert weight int32 -> bf16 (exact).
// ---------------------------------------------------------------------------
#define XB (MT * KTOT / 8 / 256)   // 16384 blocks
#define WB (NT * KTOT / 8 / 256)   // 8192 blocks

__global__ void prepack_kernel(const float4* __restrict__ x,
                               const int4* __restrict__ w,
                               const float* __restrict__ in_scale) {
    int b = blockIdx.x;
    __nv_bfloat16 o[8];
    if (b < XB) {
        int i = b * 256 + threadIdx.x;
        float s = *in_scale;
        float4 v0 = x[i * 2], v1 = x[i * 2 + 1];
        o[0] = __float2bfloat16(fminf(fmaxf(rintf(v0.x / s), -128.0f), 127.0f));
        o[1] = __float2bfloat16(fminf(fmaxf(rintf(v0.y / s), -128.0f), 127.0f));
        o[2] = __float2bfloat16(fminf(fmaxf(rintf(v0.z / s), -128.0f), 127.0f));
        o[3] = __float2bfloat16(fminf(fmaxf(rintf(v0.w / s), -128.0f), 127.0f));
        o[4] = __float2bfloat16(fminf(fmaxf(rintf(v1.x / s), -128.0f), 127.0f));
        o[5] = __float2bfloat16(fminf(fmaxf(rintf(v1.y / s), -128.0f), 127.0f));
        o[6] = __float2bfloat16(fminf(fmaxf(rintf(v1.z / s), -128.0f), 127.0f));
        o[7] = __float2bfloat16(fminf(fmaxf(rintf(v1.w / s), -128.0f), 127.0f));
        *(uint4*)(g_a + (size_t)i * 8) = *(const uint4*)o;
    } else {
        int i = (b - XB) * 256 + threadIdx.x;
        int4 v0 = w[i * 2], v1 = w[i * 2 + 1];
        o[0] = __float2bfloat16((float)v0.x);
        o[1] = __float2bfloat16((float)v0.y);
        o[2] = __float2bfloat16((float)v0.z);
        o[3] = __float2bfloat16((float)v0.w);
        o[4] = __float2bfloat16((float)v1.x);
        o[5] = __float2bfloat16((float)v1.y);
        o[6] = __float2bfloat16((float)v1.z);
        o[7] = __float2bfloat16((float)v1.w);
        *(uint4*)(g_w + (size_t)i * 8) = *(const uint4*)o;
    }
}

// ---------------------------------------------------------------------------
// bf16 HMMA GEMM: C[m,n] = sum_k A[m,k]*W[n,k] (f32 acc), then * (is*ws).
// BM=128 x BN=128 per CTA, 256 threads = 2(m) x 4(n) warps of 64x32.
// A-fragment loads interleaved with MMA groups; constant swizzle scalars.
// Smem: 128B rows, SWZ swizzle; stage s at s*32768, A then B (at +16384).
// ---------------------------------------------------------------------------
extern __shared__ char dyn_smem[];

__global__ __launch_bounds__(256, 2)
void gemm_hmma_kernel(float* __restrict__ C,
                      const float* __restrict__ w_scale,
                      const float* __restrict__ in_scale) {
    const uint32_t sb = smem_u32(dyn_smem);
    const int tid = threadIdx.x;
    const int wid = tid >> 5;
    const int lid = tid & 31;
    const int mw = wid >> 2;          // 0..1  (64 rows each)
    const int nw = wid & 3;           // 0..3  (32 cols each)

    const int tiles_m = MT / BM;      // 64, bm-fastest for L2 reuse of B panel
    const int bm = blockIdx.x % tiles_m;
    const int bn = blockIdx.x / tiles_m;

    const __nv_bfloat16* __restrict__ Ab = g_a + (size_t)(bm * BM) * KTOT;
    const __nv_bfloat16* __restrict__ Bb = g_w + (size_t)(bn * BN) * KTOT;

    // ---- cp.async staging: 2048 chunks of 16B per stage, 8 per thread ----
    auto load_stage = [&](int kt, int buf) {
        const uint32_t base = sb + buf * STAGE_BYTES;
        const int kof = kt * BK;
#pragma unroll
        for (int it = 0; it < 8; ++it) {
            int q = tid + it * 256;
            uint32_t dst;
            const __nv_bfloat16* src;
            if (q < 1024) {           // A: 128 rows x 8 chunks
                int row = q >> 3, c = q & 7;
                dst = base + SWZ(row * 128 + c * 16);
                src = Ab + (size_t)row * KTOT + kof + c * 8;
            } else {                  // B: 128 rows x 8 chunks
                int p = q - 1024;
                int row = p >> 3, c = p & 7;
                dst = base + BM * BK * 2 + SWZ(row * 128 + c * 16);
                src = Bb + (size_t)row * KTOT + kof + c * 8;
            }
            CP_ASYNC16(dst, src);
        }
        CP_COMMIT();
    };

    // ---- per-lane ldmatrix addressing (swizzle term is mi/np-invariant) ----
    const int rlA = lid & 15;                        // A x4: m16 x k16
    const int cbA = lid >> 4;
    const int rlB = (lid & 7) | ((lid >> 4) << 3);   // B x4: n16 x k16
    const int cbB = (lid >> 3) & 1;
    const int aswz = rlA & 7;                        // == row&7 for every mi
    const int bswz = rlB & 7;                        // == row&7 for every np
    const uint32_t abase = (uint32_t)(mw * 64 + rlA) * 128;               // + mi*2048
    const uint32_t bbase = BM * BK * 2 + (uint32_t)(nw * 32 + rlB) * 128; // + np*2048

    float acc[4][4][4];
#pragma unroll
    for (int mi = 0; mi < 4; ++mi)
#pragma unroll
        for (int nt = 0; nt < 4; ++nt)
#pragma unroll
            for (int j = 0; j < 4; ++j) acc[mi][nt][j] = 0.0f;

    // ---- pipeline prologue: 2 stages in flight ----
    load_stage(0, 0);
    load_stage(1, 1);

    for (int kt = 0; kt < NITER; ++kt) {
        if (kt < NITER - 1) { CP_WAIT(1); } else { CP_WAIT(0); }
        __syncthreads();

        if (kt + 2 < NITER) load_stage(kt + 2, (kt + 2) % NBUF);

        const uint32_t stage = sb + (kt % NBUF) * STAGE_BYTES;
#pragma unroll
        for (int ks = 0; ks < 4; ++ks) {
            const uint32_t sA = stage + abase + (uint32_t)(((2 * ks + cbA) ^ aswz) << 4);
            const uint32_t sB = stage + bbase + (uint32_t)(((2 * ks + cbB) ^ bswz) << 4);

            uint32_t bf[4][2];
#pragma unroll
            for (int np = 0; np < 2; ++np) {
                uint32_t r0, r1, r2, r3;
                ldsm_x4(r0, r1, r2, r3, sB + np * 2048);
                bf[np * 2 + 0][0] = r0; bf[np * 2 + 0][1] = r1;
                bf[np * 2 + 1][0] = r2; bf[np * 2 + 1][1] = r3;
            }

            uint32_t afc[4], afn[4];
            ldsm_x4(afc[0], afc[1], afc[2], afc[3], sA);
#pragma unroll
            for (int mi = 0; mi < 4; ++mi) {
                if (mi < 3)           // prefetch next A under this mi's MMAs
                    ldsm_x4(afn[0], afn[1], afn[2], afn[3], sA + (mi + 1) * 2048);
#pragma unroll
                for (int nt = 0; nt < 4; ++nt)
                    mma_bf16(acc[mi][nt], afc, bf[nt]);
#pragma unroll
                for (int j = 0; j < 4; ++j) afc[j] = afn[j];
            }
        }
    }

    // ---- epilogue: scale and store ----
    const float sc = (*w_scale) * (*in_scale);
    const int g = lid >> 2, tig = lid & 3;
    const int m_base = bm * BM + mw * 64;
    const int n_base = bn * BN + nw * 32;
#pragma unroll
    for (int mi = 0; mi < 4; ++mi) {
#pragma unroll
        for (int nt = 0; nt < 4; ++nt) {
            const int r0 = m_base + mi * 16 + g;
            const int col = n_base + nt * 8 + 2 * tig;
            float2 v0, v1;
            v0.x = acc[mi][nt][0] * sc; v0.y = acc[mi][nt][1] * sc;
            v1.x = acc[mi][nt][2] * sc; v1.y = acc[mi][nt][3] * sc;
            *(float2*)(C + (size_t)r0 * NT + col)       = v0;
            *(float2*)(C + (size_t)(r0 + 8) * NT + col) = v1;
        }
    }
}

// ---------------------------------------------------------------------------
// Harness entry
// Inputs: x fp32 [4,2048,4096], weight int32 [4096,4096], scale [1], input_scale [1]
// Output: fp32 [4,2048,4096]
// ---------------------------------------------------------------------------
extern "C" void kernel_launch(void* const* d_in, const int* in_sizes, int n_in,
                              void* d_out, int out_size) {
    const float* x        = (const float*)d_in[0];
    const int*   w        = (const int*)d_in[1];
    const float* w_scale  = (const float*)d_in[2];
    const float* in_scale = (const float*)d_in[3];
    float* out = (float*)d_out;
    (void)in_sizes; (void)n_in; (void)out_size;

    cudaFuncSetAttribute(gemm_hmma_kernel,
                         cudaFuncAttributeMaxDynamicSharedMemorySize, SMEM_TOTAL);

    prepack_kernel<<<XB + WB, 256>>>((const float4*)x, (const int4*)w, in_scale);

    const int grid = (MT / BM) * (NT / BN);   // 64 * 32 = 2048
    gemm_hmma_kernel<<<grid, 256, SMEM_TOTAL>>>(out, w_scale, in_scale);
}

// round 16
// speedup vs baseline: 4.0176x; 1.0036x over previous
#include <cuda_runtime.h>
#include <cuda_bf16.h>
#include <cstdint>

// Problem shape (fixed by the dataset)
#define MT 8192
#define NT 4096
#define KTOT 4096

// GEMM tiling
#define BM 128
#define BN 128
#define BK 64                 // bf16 elems per stage -> 128B rows
#define NITER (KTOT / BK)     // 64
#define NBUF 3
#define STAGE_BYTES ((BM + BN) * BK * 2)   // 32768
#define SMEM_TOTAL (NBUF * STAGE_BYTES)    // 98304 -> 2 CTAs/SM

// Packed bf16 operands (static device globals — no allocs)
__device__ __align__(16) __nv_bfloat16 g_a[(size_t)MT * KTOT];  // 64 MB
__device__ __align__(16) __nv_bfloat16 g_w[(size_t)NT * KTOT];  // 32 MB

// ---------------------------------------------------------------------------
// PTX helpers (baseline-PTX only: cp.async, ldmatrix, mma.sync bf16)
// ---------------------------------------------------------------------------
__device__ __forceinline__ uint32_t smem_u32(const void* p) {
    uint32_t a;
    asm("{ .reg .u64 t; cvta.to.shared.u64 t, %1; cvt.u32.u64 %0, t; }" : "=r"(a) : "l"(p));
    return a;
}
#define CP_ASYNC16(dst, src) \
    asm volatile("cp.async.cg.shared.global [%0], [%1], 16;" :: "r"(dst), "l"(src) : "memory")
#define CP_COMMIT()  asm volatile("cp.async.commit_group;" ::: "memory")
#define CP_WAIT(n)   asm volatile("cp.async.wait_group %0;" :: "n"(n) : "memory")

// byte-offset swizzle for 128B rows (8 x 16B chunks): chunk ^= (row & 7)
#define SWZ(o) ((o) ^ (((o) >> 3) & 0x70))

__device__ __forceinline__ void ldsm_x4(uint32_t& r0, uint32_t& r1, uint32_t& r2, uint32_t& r3,
                                        uint32_t addr) {
    asm volatile("ldmatrix.sync.aligned.m8n8.x4.shared.b16 {%0,%1,%2,%3}, [%4];"
                 : "=r"(r0), "=r"(r1), "=r"(r2), "=r"(r3) : "r"(addr));
}
__device__ __forceinline__ void mma_bf16(float* c, const uint32_t* a, const uint32_t* b) {
    asm volatile(
        "mma.sync.aligned.m16n8k16.row.col.f32.bf16.bf16.f32 "
        "{%0,%1,%2,%3}, {%4,%5,%6,%7}, {%8,%9}, {%0,%1,%2,%3};"
        : "+f"(c[0]), "+f"(c[1]), "+f"(c[2]), "+f"(c[3])
        : "r"(a[0]), "r"(a[1]), "r"(a[2]), "r"(a[3]), "r"(b[0]), "r"(b[1]));
}
// C store with evict-first policy: keep A/W panels resident in L2
__device__ __forceinline__ void stg_cs_v2(float* p, float x, float y) {
    asm volatile("st.global.cs.v2.f32 [%0], {%1, %2};" :: "l"(p), "f"(x), "f"(y) : "memory");
}

// ---------------------------------------------------------------------------
// Fused pre-pass: blocks [0, XB) quantize x fp32 -> bf16 (exact integers,
// matching clip(round(x/input_scale),-128,127), rintf = half-even like jnp);
// blocks [XB, XB+WB) convert weight int32 -> bf16 (exact).
// ---------------------------------------------------------------------------
#define XB (MT * KTOT / 8 / 256)   // 16384 blocks
#define WB (NT * KTOT / 8 / 256)   // 8192 blocks

__global__ void prepack_kernel(const float4* __restrict__ x,
                               const int4* __restrict__ w,
                               const float* __restrict__ in_scale) {
    int b = blockIdx.x;
    __nv_bfloat16 o[8];
    if (b < XB) {
        int i = b * 256 + threadIdx.x;
        float s = *in_scale;
        float4 v0 = x[i * 2], v1 = x[i * 2 + 1];
        o[0] = __float2bfloat16(fminf(fmaxf(rintf(v0.x / s), -128.0f), 127.0f));
        o[1] = __float2bfloat16(fminf(fmaxf(rintf(v0.y / s), -128.0f), 127.0f));
        o[2] = __float2bfloat16(fminf(fmaxf(rintf(v0.z / s), -128.0f), 127.0f));
        o[3] = __float2bfloat16(fminf(fmaxf(rintf(v0.w / s), -128.0f), 127.0f));
        o[4] = __float2bfloat16(fminf(fmaxf(rintf(v1.x / s), -128.0f), 127.0f));
        o[5] = __float2bfloat16(fminf(fmaxf(rintf(v1.y / s), -128.0f), 127.0f));
        o[6] = __float2bfloat16(fminf(fmaxf(rintf(v1.z / s), -128.0f), 127.0f));
        o[7] = __float2bfloat16(fminf(fmaxf(rintf(v1.w / s), -128.0f), 127.0f));
        *(uint4*)(g_a + (size_t)i * 8) = *(const uint4*)o;
    } else {
        int i = (b - XB) * 256 + threadIdx.x;
        int4 v0 = w[i * 2], v1 = w[i * 2 + 1];
        o[0] = __float2bfloat16((float)v0.x);
        o[1] = __float2bfloat16((float)v0.y);
        o[2] = __float2bfloat16((float)v0.z);
        o[3] = __float2bfloat16((float)v0.w);
        o[4] = __float2bfloat16((float)v1.x);
        o[5] = __float2bfloat16((float)v1.y);
        o[6] = __float2bfloat16((float)v1.z);
        o[7] = __float2bfloat16((float)v1.w);
        *(uint4*)(g_w + (size_t)i * 8) = *(const uint4*)o;
    }
}

// ---------------------------------------------------------------------------
// bf16 HMMA GEMM: C[m,n] = sum_k A[m,k]*W[n,k] (f32 acc), then * (is*ws).
// BM=128 x BN=128 per CTA, 256 threads = 2(m) x 4(n) warps of 64x32.
// ks-head LDSM chain A0->B0->B1 (first MMA depends on loads 1+2, not 3+4);
// A-stream with explicit 2-way parity; C stored with evict-first policy.
// Smem: 128B rows, SWZ swizzle; stage s at s*32768, A then B (at +16384).
// ---------------------------------------------------------------------------
extern __shared__ char dyn_smem[];

__global__ __launch_bounds__(256, 2)
void gemm_hmma_kernel(float* __restrict__ C,
                      const float* __restrict__ w_scale,
                      const float* __restrict__ in_scale) {
    const uint32_t sb = smem_u32(dyn_smem);
    const int tid = threadIdx.x;
    const int wid = tid >> 5;
    const int lid = tid & 31;
    const int mw = wid >> 2;          // 0..1  (64 rows each)
    const int nw = wid & 3;           // 0..3  (32 cols each)

    const int tiles_m = MT / BM;      // 64, bm-fastest for L2 reuse of B panel
    const int bm = blockIdx.x % tiles_m;
    const int bn = blockIdx.x / tiles_m;

    const __nv_bfloat16* __restrict__ Ab = g_a + (size_t)(bm * BM) * KTOT;
    const __nv_bfloat16* __restrict__ Bb = g_w + (size_t)(bn * BN) * KTOT;

    // ---- cp.async staging: 2048 chunks of 16B per stage, 8 per thread ----
    auto load_stage = [&](int kt, int buf) {
        const uint32_t base = sb + buf * STAGE_BYTES;
        const int kof = kt * BK;
#pragma unroll
        for (int it = 0; it < 8; ++it) {
            int q = tid + it * 256;
            uint32_t dst;
            const __nv_bfloat16* src;
            if (q < 1024) {           // A: 128 rows x 8 chunks
                int row = q >> 3, c = q & 7;
                dst = base + SWZ(row * 128 + c * 16);
                src = Ab + (size_t)row * KTOT + kof + c * 8;
            } else {                  // B: 128 rows x 8 chunks
                int p = q - 1024;
                int row = p >> 3, c = p & 7;
                dst = base + BM * BK * 2 + SWZ(row * 128 + c * 16);
                src = Bb + (size_t)row * KTOT + kof + c * 8;
            }
            CP_ASYNC16(dst, src);
        }
        CP_COMMIT();
    };

    // ---- per-lane ldmatrix addressing (swizzle term is mi/np-invariant) ----
    const int rlA = lid & 15;                        // A x4: m16 x k16
    const int cbA = lid >> 4;
    const int rlB = (lid & 7) | ((lid >> 4) << 3);   // B x4: n16 x k16
    const int cbB = (lid >> 3) & 1;
    const int aswz = rlA & 7;
    const int bswz = rlB & 7;
    const uint32_t abase = (uint32_t)(mw * 64 + rlA) * 128;               // + mi*2048
    const uint32_t bbase = BM * BK * 2 + (uint32_t)(nw * 32 + rlB) * 128; // + np*2048

    float acc[4][4][4];
#pragma unroll
    for (int mi = 0; mi < 4; ++mi)
#pragma unroll
        for (int nt = 0; nt < 4; ++nt)
#pragma unroll
            for (int j = 0; j < 4; ++j) acc[mi][nt][j] = 0.0f;

    // ---- pipeline prologue: 2 stages in flight ----
    load_stage(0, 0);
    load_stage(1, 1);

    for (int kt = 0; kt < NITER; ++kt) {
        if (kt < NITER - 1) { CP_WAIT(1); } else { CP_WAIT(0); }
        __syncthreads();

        if (kt + 2 < NITER) load_stage(kt + 2, (kt + 2) % NBUF);

        const uint32_t stage = sb + (kt % NBUF) * STAGE_BYTES;
#pragma unroll
        for (int ks = 0; ks < 4; ++ks) {
            const uint32_t sA = stage + abase + (uint32_t)(((2 * ks + cbA) ^ aswz) << 4);
            const uint32_t sB = stage + bbase + (uint32_t)(((2 * ks + cbB) ^ bswz) << 4);

            uint32_t a0[4], a1[4], bf[4][2];
            // A0 first, then B0, B1: first MMA depends on loads #1+#2 only
            ldsm_x4(a0[0], a0[1], a0[2], a0[3], sA);
            {
                uint32_t r0, r1, r2, r3;
                ldsm_x4(r0, r1, r2, r3, sB);
                bf[0][0] = r0; bf[0][1] = r1; bf[1][0] = r2; bf[1][1] = r3;
                ldsm_x4(r0, r1, r2, r3, sB + 2048);
                bf[2][0] = r0; bf[2][1] = r1; bf[3][0] = r2; bf[3][1] = r3;
            }
            // mi=0 (a0 live), prefetch a1
            ldsm_x4(a1[0], a1[1], a1[2], a1[3], sA + 2048);
#pragma unroll
            for (int nt = 0; nt < 4; ++nt) mma_bf16(acc[0][nt], a0, bf[nt]);
            // mi=1 (a1 live), prefetch a0' = A2
            ldsm_x4(a0[0], a0[1], a0[2], a0[3], sA + 2 * 2048);
#pragma unroll
            for (int nt = 0; nt < 4; ++nt) mma_bf16(acc[1][nt], a1, bf[nt]);
            // mi=2 (a0 live), prefetch a1' = A3
            ldsm_x4(a1[0], a1[1], a1[2], a1[3], sA + 3 * 2048);
#pragma unroll
            for (int nt = 0; nt < 4; ++nt) mma_bf16(acc[2][nt], a0, bf[nt]);
            // mi=3 (a1 live)
#pragma unroll
            for (int nt = 0; nt < 4; ++nt) mma_bf16(acc[3][nt], a1, bf[nt]);
        }
    }

    // ---- epilogue: scale and store (evict-first; protect A/W in L2) ----
    const float sc = (*w_scale) * (*in_scale);
    const int g = lid >> 2, tig = lid & 3;
    const int m_base = bm * BM + mw * 64;
    const int n_base = bn * BN + nw * 32;
#pragma unroll
    for (int mi = 0; mi < 4; ++mi) {
#pragma unroll
        for (int nt = 0; nt < 4; ++nt) {
            const int r0 = m_base + mi * 16 + g;
            const int col = n_base + nt * 8 + 2 * tig;
            stg_cs_v2(C + (size_t)r0 * NT + col,
                      acc[mi][nt][0] * sc, acc[mi][nt][1] * sc);
            stg_cs_v2(C + (size_t)(r0 + 8) * NT + col,
                      acc[mi][nt][2] * sc, acc[mi][nt][3] * sc);
        }
    }
}

// ---------------------------------------------------------------------------
// Harness entry
// Inputs: x fp32 [4,2048,4096], weight int32 [4096,4096], scale [1], input_scale [1]
// Output: fp32 [4,2048,4096]
// ---------------------------------------------------------------------------
extern "C" void kernel_launch(void* const* d_in, const int* in_sizes, int n_in,
                              void* d_out, int out_size) {
    const float* x        = (const float*)d_in[0];
    const int*   w        = (const int*)d_in[1];
    const float* w_scale  = (const float*)d_in[2];
    const float* in_scale = (const float*)d_in[3];
    float* out = (float*)d_out;
    (void)in_sizes; (void)n_in; (void)out_size;

    cudaFuncSetAttribute(gemm_hmma_kernel,
                         cudaFuncAttributeMaxDynamicSharedMemorySize, SMEM_TOTAL);

    prepack_kernel<<<XB + WB, 256>>>((const float4*)x, (const int4*)w, in_scale);

    const int grid = (MT / BM) * (NT / BN);   // 64 * 32 = 2048
    gemm_hmma_kernel<<<grid, 256, SMEM_TOTAL>>>(out, w_scale, in_scale);
}